// round 13
// baseline (speedup 1.0000x reference)
#include <cuda_runtime.h>

#define NN 256
#define TT 1500
#define R 4
#define CT (32 * R)                  // 128 steps per warp-chunk
#define NFULL (TT / CT)              // 11 full chunks (tail: 92 steps, lanes 0..22)
#define PLANE (NN * TT)

// One cell's 128-step chunk, 6 shfl. Carry-baked truncated scan (window
// 8 lanes = 32 steps; dropped terms <= 0.625^32 ~ 3e-7); final rotate shfl
// hands lanes 1..31 their v_start and lane 0 the next carry in one op.
template<bool TAIL>
__device__ __forceinline__ void cell_chunk(const float4 x, const float4 y,
                                           const bool act, const int lane,
                                           float& carry, float* __restrict__ o) {
    float a0, a1, a2, a3, A, B;
    if (!TAIL || act) {
        a0 = x.x + y.x;  a1 = x.y + y.y;  a2 = x.z + y.z;  a3 = x.w + y.w;
        A = a0; B = fmaf(-20.0f, a0, 12.5f);
        B = fmaf(a1, B, fmaf(-20.0f, a1, 12.5f)); A *= a1;
        B = fmaf(a2, B, fmaf(-20.0f, a2, 12.5f)); A *= a2;
        B = fmaf(a3, B, fmaf(-20.0f, a3, 12.5f)); A *= a3;
    } else {
        A = 1.0f; B = 0.0f;
        a0 = a1 = a2 = a3 = 1.0f;
    }

    if (lane == 0) B = fmaf(A, carry, B);        // bake carry into lane 0

    float Au, Bu;
    Au = __shfl_up_sync(0xffffffffu, A, 1);
    Bu = __shfl_up_sync(0xffffffffu, B, 1);
    if (lane >= 1) { B = fmaf(A, Bu, B); A *= Au; }
    Au = __shfl_up_sync(0xffffffffu, A, 2);
    Bu = __shfl_up_sync(0xffffffffu, B, 2);
    if (lane >= 2) { B = fmaf(A, Bu, B); A *= Au; }
    Bu = __shfl_up_sync(0xffffffffu, B, 4);
    if (lane >= 4) { B = fmaf(A, Bu, B); }

    float rot = __shfl_sync(0xffffffffu, B, (lane + 31) & 31);
    float v;
    if (lane == 0) { v = carry; carry = rot; }   // rot == B_31 == next carry
    else           { v = rot; }

    if (!TAIL || act) {
        float4 r;
        v = fmaf(a0, v, fmaf(-20.0f, a0, 12.5f)); r.x = v;
        v = fmaf(a1, v, fmaf(-20.0f, a1, 12.5f)); r.y = v;
        v = fmaf(a2, v, fmaf(-20.0f, a2, 12.5f)); r.z = v;
        v = fmaf(a3, v, fmaf(-20.0f, a3, 12.5f)); r.w = v;
        __stcs((float4*)o, r);                    // streaming: never re-read
    }
}

// load u chunk -> half-coefficient q = 0.3125 - c*sat(u)
__device__ __forceinline__ float4 load_q(const float* __restrict__ p, const float c) {
    float4 x = *(const float4*)p;
    float4 q;
    q.x = fmaf(-c, __saturatef(x.x), 0.3125f);
    q.y = fmaf(-c, __saturatef(x.y), 0.3125f);
    q.z = fmaf(-c, __saturatef(x.z), 0.3125f);
    q.w = fmaf(-c, __saturatef(x.w), 0.3125f);
    return q;
}

// Fused, 2x2 cell tile per warp. 4 independent load pointers (MLP), ONE
// store base with compile-time immediate offsets (regs), pointer-advance
// loop (no per-chunk address IMADs).
__global__ __launch_bounds__(256, 5) void sim_kernel(
    const float* __restrict__ u0, const float* __restrict__ u1,
    const float* __restrict__ ksyn, float* __restrict__ out)
{
    const int lane = threadIdx.x & 31;
    const int w    = threadIdx.x >> 5;              // 0..7
    const int i0 = blockIdx.y * 4 + (w >> 2) * 2;
    const int j0 = blockIdx.x * 8 + (w & 3) * 2;

    const float ki0 = ksyn[i0],      ki1 = ksyn[i0 + 1];
    const float kj0 = ksyn[NN + j0], kj1 = ksyn[NN + j0 + 1];
    const float ci0 = 0.075f * ki0 / (20.0f - 2.0f * ki0);
    const float ci1 = 0.075f * ki1 / (20.0f - 2.0f * ki1);
    const float cj0 = 0.075f * kj0 / (20.0f - 2.0f * kj0);
    const float cj1 = 0.075f * kj1 / (20.0f - 2.0f * kj1);

    const int toff = lane * R;
    const float* __restrict__ xi0 = u0 + i0 * TT + toff;
    const float* __restrict__ xi1 = xi0 + TT;
    const float* __restrict__ yj0 = u1 + j0 * TT + toff;
    const float* __restrict__ yj1 = yj0 + TT;
    float* __restrict__ ob = out + (i0 * NN + j0) * TT + toff;

    float c00 = 0.0f, c01 = 0.0f, c10 = 0.0f, c11 = 0.0f;

    #pragma unroll 1
    for (int c = 0; c < NFULL; c++) {
        float4 qx0 = load_q(xi0, ci0);
        float4 qx1 = load_q(xi1, ci1);
        float4 qy0 = load_q(yj0, cj0);
        float4 qy1 = load_q(yj1, cj1);

        cell_chunk<false>(qx0, qy0, true, lane, c00, ob);
        cell_chunk<false>(qx0, qy1, true, lane, c01, ob + TT);
        cell_chunk<false>(qx1, qy0, true, lane, c10, ob + PLANE);
        cell_chunk<false>(qx1, qy1, true, lane, c11, ob + PLANE + TT);

        xi0 += CT; xi1 += CT; yj0 += CT; yj1 += CT; ob += CT;
    }

    // tail chunk: steps 1408..1499, lanes 0..22 active (whole float4s)
    {
        const bool act = (NFULL * CT + toff < TT);

        float4 qx0, qx1, qy0, qy1;
        if (act) {
            qx0 = load_q(xi0, ci0);
            qx1 = load_q(xi1, ci1);
            qy0 = load_q(yj0, cj0);
            qy1 = load_q(yj1, cj1);
        }

        cell_chunk<true>(qx0, qy0, act, lane, c00, ob);
        cell_chunk<true>(qx0, qy1, act, lane, c01, ob + TT);
        cell_chunk<true>(qx1, qy0, act, lane, c10, ob + PLANE);
        cell_chunk<true>(qx1, qy1, act, lane, c11, ob + PLANE + TT);
    }
}

extern "C" void kernel_launch(void* const* d_in, const int* in_sizes, int n_in,
                              void* d_out, int out_size) {
    const float* u0   = (const float*)d_in[0];   // u_pre_0 (N,T)
    const float* u1   = (const float*)d_in[1];   // u_pre_1 (N,T)
    const float* ksyn = (const float*)d_in[2];   // k_syn (2,N)
    float* out = (float*)d_out;                  // (N,N,T) fp32

    dim3 grid(NN / 8, NN / 4);                   // 32 x 64 = 2048 blocks
    sim_kernel<<<grid, 256>>>(u0, u1, ksyn, out);
}

// round 14
// speedup vs baseline: 1.0180x; 1.0180x over previous
#include <cuda_runtime.h>

#define NN 256
#define TT 1500
#define R 4
#define CT (32 * R)                  // 128 steps per warp-chunk
#define NFULL (TT / CT)              // 11 full chunks (tail: 92 steps, lanes 0..22)
#define PLANE (NN * TT)

// One cell's 128-step chunk, 6 shfl. Carry-baked truncated scan (window
// 8 lanes = 32 steps; dropped terms <= 0.625^32 ~ 3e-7); final rotate shfl
// hands lanes 1..31 their v_start and lane 0 the next carry in one op.
template<bool TAIL>
__device__ __forceinline__ void cell_chunk(const float4 x, const float4 y,
                                           const bool act, const int lane,
                                           float& carry, float* __restrict__ o) {
    float a0, a1, a2, a3, A, B;
    if (!TAIL || act) {
        a0 = x.x + y.x;  a1 = x.y + y.y;  a2 = x.z + y.z;  a3 = x.w + y.w;
        A = a0; B = fmaf(-20.0f, a0, 12.5f);
        B = fmaf(a1, B, fmaf(-20.0f, a1, 12.5f)); A *= a1;
        B = fmaf(a2, B, fmaf(-20.0f, a2, 12.5f)); A *= a2;
        B = fmaf(a3, B, fmaf(-20.0f, a3, 12.5f)); A *= a3;
    } else {
        A = 1.0f; B = 0.0f;
        a0 = a1 = a2 = a3 = 1.0f;
    }

    if (lane == 0) B = fmaf(A, carry, B);        // bake carry into lane 0

    float Au, Bu;
    Au = __shfl_up_sync(0xffffffffu, A, 1);
    Bu = __shfl_up_sync(0xffffffffu, B, 1);
    if (lane >= 1) { B = fmaf(A, Bu, B); A *= Au; }
    Au = __shfl_up_sync(0xffffffffu, A, 2);
    Bu = __shfl_up_sync(0xffffffffu, B, 2);
    if (lane >= 2) { B = fmaf(A, Bu, B); A *= Au; }
    Bu = __shfl_up_sync(0xffffffffu, B, 4);
    if (lane >= 4) { B = fmaf(A, Bu, B); }

    float rot = __shfl_sync(0xffffffffu, B, (lane + 31) & 31);
    float v;
    if (lane == 0) { v = carry; carry = rot; }   // rot == B_31 == next carry
    else           { v = rot; }

    if (!TAIL || act) {
        float4 r;
        v = fmaf(a0, v, fmaf(-20.0f, a0, 12.5f)); r.x = v;
        v = fmaf(a1, v, fmaf(-20.0f, a1, 12.5f)); r.y = v;
        v = fmaf(a2, v, fmaf(-20.0f, a2, 12.5f)); r.z = v;
        v = fmaf(a3, v, fmaf(-20.0f, a3, 12.5f)); r.w = v;
        __stcs((float4*)o, r);                    // streaming: never re-read
    }
}

// load u chunk -> half-coefficient q = 0.3125 - c*sat(u)
__device__ __forceinline__ float4 load_q(const float* __restrict__ p, const float c) {
    float4 x = *(const float4*)p;
    float4 q;
    q.x = fmaf(-c, __saturatef(x.x), 0.3125f);
    q.y = fmaf(-c, __saturatef(x.y), 0.3125f);
    q.z = fmaf(-c, __saturatef(x.z), 0.3125f);
    q.w = fmaf(-c, __saturatef(x.w), 0.3125f);
    return q;
}

// Fused 2x2 tile per warp, SOFTWARE-PIPELINED: chunk c+1's loads are issued
// before chunk c's scan/store work, hiding L2/DRAM latency behind compute.
// unroll 2 makes the double-buffer rotation free.
__global__ __launch_bounds__(256) void sim_kernel(
    const float* __restrict__ u0, const float* __restrict__ u1,
    const float* __restrict__ ksyn, float* __restrict__ out)
{
    const int lane = threadIdx.x & 31;
    const int w    = threadIdx.x >> 5;              // 0..7
    const int i0 = blockIdx.y * 4 + (w >> 2) * 2;
    const int j0 = blockIdx.x * 8 + (w & 3) * 2;

    const float ki0 = ksyn[i0],      ki1 = ksyn[i0 + 1];
    const float kj0 = ksyn[NN + j0], kj1 = ksyn[NN + j0 + 1];
    const float ci0 = 0.075f * ki0 / (20.0f - 2.0f * ki0);
    const float ci1 = 0.075f * ki1 / (20.0f - 2.0f * ki1);
    const float cj0 = 0.075f * kj0 / (20.0f - 2.0f * kj0);
    const float cj1 = 0.075f * kj1 / (20.0f - 2.0f * kj1);

    const int toff = lane * R;
    const float* __restrict__ xi0 = u0 + i0 * TT + toff;
    const float* __restrict__ xi1 = xi0 + TT;
    const float* __restrict__ yj0 = u1 + j0 * TT + toff;
    const float* __restrict__ yj1 = yj0 + TT;
    float* __restrict__ ob = out + (i0 * NN + j0) * TT + toff;

    float c00 = 0.0f, c01 = 0.0f, c10 = 0.0f, c11 = 0.0f;

    // preload chunk 0
    float4 qx0 = load_q(xi0, ci0);
    float4 qx1 = load_q(xi1, ci1);
    float4 qy0 = load_q(yj0, cj0);
    float4 qy1 = load_q(yj1, cj1);

    #pragma unroll 2
    for (int c = 0; c < NFULL - 1; c++) {
        xi0 += CT; xi1 += CT; yj0 += CT; yj1 += CT;

        // issue next chunk's loads BEFORE consuming current chunk
        float4 nx0 = load_q(xi0, ci0);
        float4 nx1 = load_q(xi1, ci1);
        float4 ny0 = load_q(yj0, cj0);
        float4 ny1 = load_q(yj1, cj1);

        cell_chunk<false>(qx0, qy0, true, lane, c00, ob);
        cell_chunk<false>(qx0, qy1, true, lane, c01, ob + TT);
        cell_chunk<false>(qx1, qy0, true, lane, c10, ob + PLANE);
        cell_chunk<false>(qx1, qy1, true, lane, c11, ob + PLANE + TT);
        ob += CT;

        qx0 = nx0; qx1 = nx1; qy0 = ny0; qy1 = ny1;
    }

    // last full chunk (already loaded)
    cell_chunk<false>(qx0, qy0, true, lane, c00, ob);
    cell_chunk<false>(qx0, qy1, true, lane, c01, ob + TT);
    cell_chunk<false>(qx1, qy0, true, lane, c10, ob + PLANE);
    cell_chunk<false>(qx1, qy1, true, lane, c11, ob + PLANE + TT);
    ob += CT;

    // tail chunk: steps 1408..1499, lanes 0..22 active (whole float4s)
    {
        xi0 += CT; xi1 += CT; yj0 += CT; yj1 += CT;
        const bool act = (NFULL * CT + toff < TT);

        if (act) {
            qx0 = load_q(xi0, ci0);
            qx1 = load_q(xi1, ci1);
            qy0 = load_q(yj0, cj0);
            qy1 = load_q(yj1, cj1);
        }

        cell_chunk<true>(qx0, qy0, act, lane, c00, ob);
        cell_chunk<true>(qx0, qy1, act, lane, c01, ob + TT);
        cell_chunk<true>(qx1, qy0, act, lane, c10, ob + PLANE);
        cell_chunk<true>(qx1, qy1, act, lane, c11, ob + PLANE + TT);
    }
}

extern "C" void kernel_launch(void* const* d_in, const int* in_sizes, int n_in,
                              void* d_out, int out_size) {
    const float* u0   = (const float*)d_in[0];   // u_pre_0 (N,T)
    const float* u1   = (const float*)d_in[1];   // u_pre_1 (N,T)
    const float* ksyn = (const float*)d_in[2];   // k_syn (2,N)
    float* out = (float*)d_out;                  // (N,N,T) fp32

    dim3 grid(NN / 8, NN / 4);                   // 32 x 64 = 2048 blocks
    sim_kernel<<<grid, 256>>>(u0, u1, ksyn, out);
}